// round 4
// baseline (speedup 1.0000x reference)
#include <cuda_runtime.h>

// Problem constants
#define BB 8
#define LL 1024
#define DM 1024
#define NH 16
#define DV 64
#define DTT 64

// Scratch (device globals: allocation-free contract)
__device__ float g_q[BB * NH * LL * DV];          // 32 MB  (b,h,l,64)
__device__ float g_k[BB * NH * LL * DV];          // 32 MB
__device__ float g_v[BB * NH * LL * DV];          // 32 MB
__device__ float g_t[BB * LL * DTT];              // 2 MB   (b,l,64)
__device__ float g_TT[BB * LL * LL];              // 32 MB  (b,q,k) t.t' shared across heads
__device__ float g_S[(size_t)BB * NH * LL * LL];  // 512 MB (bh,q,k)
__device__ float g_x[BB * LL * DM];               // 32 MB  (b,q,h*64+d)

enum { EPI_PLAIN = 0, EPI_HEADS = 1, EPI_ADD = 2 };

// C[m,n] = sum_k A[m,k]*B[n,k]  (NT), 128x128 tile, 8x8 microtile, 256 thr
template <int EPI, bool HAS_BIAS>
__global__ void __launch_bounds__(256)
sgemm_nt(const float* __restrict__ A, const float* __restrict__ B,
         const float* __restrict__ bias, const float* __restrict__ addend,
         float* __restrict__ C, int M, int N, int K,
         long aBS, long bBS, long cBS, long addBS)
{
    __shared__ float As[8][128];
    __shared__ float Bs[8][128];
    const int z = blockIdx.z;
    A += (long)z * aBS;
    B += (long)z * bBS;
    const int m0 = blockIdx.y * 128;
    const int n0 = blockIdx.x * 128;
    const int tid = threadIdx.x;
    const int tx = tid & 15;
    const int ty = tid >> 4;
    const int lrow = tid & 127;
    const int lseg = tid >> 7;

    const float* Ald = A + (long)(m0 + lrow) * K + lseg * 4;
    const float* Bld = B + (long)(n0 + lrow) * K + lseg * 4;

    float acc[8][8];
#pragma unroll
    for (int i = 0; i < 8; i++)
#pragma unroll
        for (int j = 0; j < 8; j++) acc[i][j] = 0.f;

    for (int kt = 0; kt < K; kt += 8) {
        float4 av = *(const float4*)(Ald + kt);
        float4 bv = *(const float4*)(Bld + kt);
        __syncthreads();
        As[lseg * 4 + 0][lrow] = av.x;
        As[lseg * 4 + 1][lrow] = av.y;
        As[lseg * 4 + 2][lrow] = av.z;
        As[lseg * 4 + 3][lrow] = av.w;
        Bs[lseg * 4 + 0][lrow] = bv.x;
        Bs[lseg * 4 + 1][lrow] = bv.y;
        Bs[lseg * 4 + 2][lrow] = bv.z;
        Bs[lseg * 4 + 3][lrow] = bv.w;
        __syncthreads();
#pragma unroll
        for (int kk = 0; kk < 8; kk++) {
            float a[8], b[8];
            *(float4*)(a)     = *(const float4*)&As[kk][ty * 4];
            *(float4*)(a + 4) = *(const float4*)&As[kk][64 + ty * 4];
            *(float4*)(b)     = *(const float4*)&Bs[kk][tx * 4];
            *(float4*)(b + 4) = *(const float4*)&Bs[kk][64 + tx * 4];
#pragma unroll
            for (int i = 0; i < 8; i++)
#pragma unroll
                for (int j = 0; j < 8; j++) acc[i][j] += a[i] * b[j];
        }
    }

#pragma unroll
    for (int i = 0; i < 8; i++) {
        int m = m0 + (i < 4 ? ty * 4 + i : 60 + ty * 4 + i);
#pragma unroll
        for (int j = 0; j < 8; j++) {
            int n = n0 + (j < 4 ? tx * 4 + j : 60 + tx * 4 + j);
            float v = acc[i][j];
            if (HAS_BIAS) v += bias[n];
            if (EPI == EPI_PLAIN) {
                C[(long)z * cBS + (long)m * N + n] = v;
            } else if (EPI == EPI_ADD) {
                long off = (long)m * N + n;
                C[(long)z * cBS + off] = v + addend[(long)(z >> 4) * addBS + off];
            } else {  // EPI_HEADS: (b*L+l, h*64+d) -> (b,h,l,d) stride 64
                int b_ = m >> 10, l_ = m & 1023, h_ = n >> 6, d_ = n & 63;
                C[((((long)(b_ * NH + h_)) << 10) + l_) * 64 + d_] = v;
            }
        }
    }
}

// X[(b,q),(h*64+d)] = sum_k P[bh,q,k] * V[bh,k,d]   (NN, N=64)
__global__ void __launch_bounds__(256)
pv_gemm(const float* __restrict__ P, const float* __restrict__ Vh, float* __restrict__ X)
{
    __shared__ float As[16][128];
    __shared__ float Bs[16][64];
    const int z = blockIdx.z;
    const float* A  = P + ((long)z << 20);
    const float* Bp = Vh + ((long)z << 16);
    const int m0 = blockIdx.y * 128;
    const int tid = threadIdx.x;
    const int tx = tid & 15, ty = tid >> 4;
    const int lrow = tid & 127, lseg = tid >> 7;
    const int bk = tid >> 4, bn = (tid & 15) * 4;
    const float* Ald = A + (long)(m0 + lrow) * 1024 + lseg * 8;

    float acc[8][4];
#pragma unroll
    for (int i = 0; i < 8; i++)
#pragma unroll
        for (int j = 0; j < 4; j++) acc[i][j] = 0.f;

    for (int kt = 0; kt < 1024; kt += 16) {
        float4 a0 = *(const float4*)(Ald + kt);
        float4 a1 = *(const float4*)(Ald + kt + 4);
        float4 bv = *(const float4*)(Bp + ((long)(kt + bk) << 6) + bn);
        __syncthreads();
        As[lseg * 8 + 0][lrow] = a0.x;
        As[lseg * 8 + 1][lrow] = a0.y;
        As[lseg * 8 + 2][lrow] = a0.z;
        As[lseg * 8 + 3][lrow] = a0.w;
        As[lseg * 8 + 4][lrow] = a1.x;
        As[lseg * 8 + 5][lrow] = a1.y;
        As[lseg * 8 + 6][lrow] = a1.z;
        As[lseg * 8 + 7][lrow] = a1.w;
        *(float4*)&Bs[bk][bn] = bv;
        __syncthreads();
#pragma unroll
        for (int kk = 0; kk < 16; kk++) {
            float a[8], bb[4];
            *(float4*)(a)     = *(const float4*)&As[kk][ty * 4];
            *(float4*)(a + 4) = *(const float4*)&As[kk][64 + ty * 4];
            *(float4*)(bb)    = *(const float4*)&Bs[kk][tx * 4];
#pragma unroll
            for (int i = 0; i < 8; i++)
#pragma unroll
                for (int j = 0; j < 4; j++) acc[i][j] += a[i] * bb[j];
        }
    }
    const int b_ = z >> 4, h_ = z & 15;
#pragma unroll
    for (int i = 0; i < 8; i++) {
        int m = m0 + (i < 4 ? ty * 4 + i : 60 + ty * 4 + i);
        float* xr = X + ((((long)(b_ << 10)) + m) << 10) + (h_ << 6) + tx * 4;
        *(float4*)xr = make_float4(acc[i][0], acc[i][1], acc[i][2], acc[i][3]);
    }
}

// t_out[b*L+l, dt] = sum_k T[b*L+l,k]*WT[dt,k] + bT[dt]  (tiny)
__global__ void __launch_bounds__(256)
tproj(const float* __restrict__ T, const float* __restrict__ WT,
      const float* __restrict__ bT, float* __restrict__ t_out)
{
    __shared__ float Ws[64][65];
    __shared__ float Ts[4][64];
    int tid = threadIdx.x;
    for (int i = tid; i < 64 * 64; i += 256) Ws[i >> 6][i & 63] = WT[i];
    int r0 = blockIdx.x * 4;
    Ts[tid >> 6][tid & 63] = T[r0 * 64 + tid];
    __syncthreads();
    int lr = tid >> 6, dt = tid & 63;
    float s = bT[dt];
#pragma unroll
    for (int k2 = 0; k2 < 64; k2++) s += Ts[lr][k2] * Ws[dt][k2];
    t_out[(r0 + lr) * 64 + dt] = s;
}

// Row softmax with scale + mask (in place on S). One block (128 thr) per row.
__global__ void __launch_bounds__(128)
softmax_kernel(float* __restrict__ S, const int* __restrict__ mask)
{
    long r = blockIdx.x;                  // r = bh*1024 + q
    int q = (int)(r & 1023);
    int b = (int)(r >> 14);               // bh >> 4
    float* row = S + (r << 10);
    const int* mrow = mask + ((((long)b) << 10) + q) * 1024;
    int tid = threadIdx.x;
    int c0 = tid * 8;
    float4 s0 = *(const float4*)(row + c0);
    float4 s1 = *(const float4*)(row + c0 + 4);
    int4 m0 = *(const int4*)(mrow + c0);
    int4 m1 = *(const int4*)(mrow + c0 + 4);
    const float sc = 0.08838834764831845f;  // 1/sqrt(128)
    float v[8];
    v[0] = (m0.x == 1) ? -1e9f : s0.x * sc;
    v[1] = (m0.y == 1) ? -1e9f : s0.y * sc;
    v[2] = (m0.z == 1) ? -1e9f : s0.z * sc;
    v[3] = (m0.w == 1) ? -1e9f : s0.w * sc;
    v[4] = (m1.x == 1) ? -1e9f : s1.x * sc;
    v[5] = (m1.y == 1) ? -1e9f : s1.y * sc;
    v[6] = (m1.z == 1) ? -1e9f : s1.z * sc;
    v[7] = (m1.w == 1) ? -1e9f : s1.w * sc;

    float mx = v[0];
#pragma unroll
    for (int i = 1; i < 8; i++) mx = fmaxf(mx, v[i]);
#pragma unroll
    for (int o = 16; o; o >>= 1) mx = fmaxf(mx, __shfl_xor_sync(0xffffffffu, mx, o));
    __shared__ float sm_[4], ss_[4];
    int lane = tid & 31, w = tid >> 5;
    if (lane == 0) sm_[w] = mx;
    __syncthreads();
    mx = fmaxf(fmaxf(sm_[0], sm_[1]), fmaxf(sm_[2], sm_[3]));

    float e[8];
    float sum = 0.f;
#pragma unroll
    for (int i = 0; i < 8; i++) { e[i] = __expf(v[i] - mx); sum += e[i]; }
#pragma unroll
    for (int o = 16; o; o >>= 1) sum += __shfl_xor_sync(0xffffffffu, sum, o);
    if (lane == 0) ss_[w] = sum;
    __syncthreads();
    sum = ss_[0] + ss_[1] + ss_[2] + ss_[3];
    float inv = 1.0f / sum;
    *(float4*)(row + c0)     = make_float4(e[0] * inv, e[1] * inv, e[2] * inv, e[3] * inv);
    *(float4*)(row + c0 + 4) = make_float4(e[4] * inv, e[5] * inv, e[6] * inv, e[7] * inv);
}

static float* symaddr(const void* sym)
{
    void* p = nullptr;
    cudaGetSymbolAddress(&p, sym);
    return (float*)p;
}

extern "C" void kernel_launch(void* const* d_in, const int* in_sizes, int n_in,
                              void* d_out, int out_size)
{
    const float* Qin  = (const float*)d_in[0];
    const float* Kin  = (const float*)d_in[1];
    const float* Vin  = (const float*)d_in[2];
    const float* Tin  = (const float*)d_in[3];
    const int*   mask = (const int*)d_in[4];
    const float* WQ = (const float*)d_in[5];
    const float* bQ = (const float*)d_in[6];
    const float* WK = (const float*)d_in[7];
    const float* bK = (const float*)d_in[8];
    const float* WV = (const float*)d_in[9];
    const float* bV = (const float*)d_in[10];
    const float* WM = (const float*)d_in[11];
    const float* bM = (const float*)d_in[12];
    const float* WT = (const float*)d_in[13];
    const float* bT = (const float*)d_in[14];
    float* out = (float*)d_out;

    float* q  = symaddr(g_q);
    float* k  = symaddr(g_k);
    float* v  = symaddr(g_v);
    float* t  = symaddr(g_t);
    float* TT = symaddr(g_TT);
    float* S  = symaddr(g_S);
    float* x  = symaddr(g_x);

    const int M = BB * LL;  // 8192
    dim3 gProj(DM / 128, M / 128, 1);  // (8, 64)

    // 1-3: Q/K/V projections -> head-split (b,h,l,64)
    sgemm_nt<EPI_HEADS, true><<<gProj, 256>>>(Qin, WQ, bQ, nullptr, q, M, DM, DM, 0, 0, 0, 0);
    sgemm_nt<EPI_HEADS, true><<<gProj, 256>>>(Kin, WK, bK, nullptr, k, M, DM, DM, 0, 0, 0, 0);
    sgemm_nt<EPI_HEADS, true><<<gProj, 256>>>(Vin, WV, bV, nullptr, v, M, DM, DM, 0, 0, 0, 0);

    // 4: temporal projection t = T @ WT.T + bT
    tproj<<<M / 4, 256>>>(Tin, WT, bT, t);

    // 5: TT[b,q,k] = t[b,q,:].t[b,k,:]  (shared across all 16 heads)
    sgemm_nt<EPI_PLAIN, false><<<dim3(8, 8, BB), 256>>>(
        t, t, nullptr, nullptr, TT, LL, LL, DTT,
        (long)LL * DTT, (long)LL * DTT, (long)LL * LL, 0);

    // 6: S[bh,q,k] = q.k (64-dim) + TT[b,q,k]
    sgemm_nt<EPI_ADD, false><<<dim3(8, 8, BB * NH), 256>>>(
        q, k, nullptr, TT, S, LL, LL, DV,
        (long)LL * DV, (long)LL * DV, (long)LL * LL, (long)LL * LL);

    // 7: scale + mask + softmax, in place
    softmax_kernel<<<BB * NH * LL, 128>>>(S, mask);

    // 8: x[b,q,h*64+d] = P @ V
    pv_gemm<<<dim3(1, 8, BB * NH), 256>>>(S, v, x);

    // 9: out = x @ WM.T + bM
    sgemm_nt<EPI_PLAIN, true><<<gProj, 256>>>(x, WM, bM, nullptr, out, M, DM, DM, 0, 0, 0, 0);
}

// round 5
// speedup vs baseline: 1.2839x; 1.2839x over previous
#include <cuda_runtime.h>
#include <mma.h>
using namespace nvcuda;

// Problem constants
#define BB 8
#define LL 1024
#define DM 1024
#define NH 16
#define DV 64
#define DTT 64

// Scratch (device globals: allocation-free contract)
__device__ float g_q[BB * NH * LL * DV];            // 32 MB  (b,h,l,64)
__device__ float g_k[BB * NH * LL * DV];            // 32 MB
__device__ float g_vt[BB * NH * DV * LL];           // 32 MB  (b,h,d,l)  V transposed
__device__ float g_t[BB * LL * DTT];                // 2 MB
__device__ float g_TT[BB * LL * LL];                // 32 MB  (b,q,k) t.t' shared across heads
__device__ float g_S[(size_t)BB * NH * LL * LL];    // 512 MB (bh,q,k)
__device__ float g_x[BB * LL * DM];                 // 32 MB
__device__ unsigned g_mp[BB * LL * (LL / 32)];      // 1 MB packed mask bits

enum { EPI_PLAIN = 0, EPI_HEADS = 1, EPI_HEADST = 2, EPI_X = 3 };

// C[m,n] = sum_k A[m,k]*B[n,k] (NT) in tf32 tensor cores.
// BM=128, BK=32, 256 threads = 8 warps as 4(m) x 2(n); warp tile 32 x WN.
// HAS_BIAS: acc initialized from replicated bias rows (value depends on n only).
// ADD_INIT: acc initialized from addend[z>>4] (row-major MxN) — used for S = qk + TT.
template <int BN, int WN, int EPI, bool HAS_BIAS, bool ADD_INIT>
__global__ void __launch_bounds__(256)
wgemm(const float* __restrict__ A, const float* __restrict__ B,
      const float* __restrict__ bias, const float* __restrict__ addend,
      float* __restrict__ C, int M, int N, int K,
      long aBS, long bBS, long cBS, long addBS)
{
    constexpr int BM = 128, BK = 32;
    constexpr int NI = WN / 16;  // n-fragments per warp (4 or 2)
    __shared__ float As[BM][BK + 4];
    __shared__ float Bs[BN][BK + 4];
    __shared__ float biasRep[16][BN + 4];

    const int z = blockIdx.z;
    A += (long)z * aBS;
    B += (long)z * bBS;
    const int m0 = blockIdx.y * BM;
    const int n0 = blockIdx.x * BN;
    const int tid = threadIdx.x;
    const int w = tid >> 5;
    const int wm = w & 3;   // warp row   (4)
    const int wn = w >> 2;  // warp col   (2)

    wmma::fragment<wmma::accumulator, 16, 16, 8, float> acc[2][NI];

    if (HAS_BIAS) {
        for (int i = tid; i < 16 * BN; i += 256)
            biasRep[i / BN][i % BN] = bias[n0 + (i % BN)];
        __syncthreads();
#pragma unroll
        for (int i = 0; i < 2; i++)
#pragma unroll
            for (int j = 0; j < NI; j++)
                wmma::load_matrix_sync(acc[i][j], &biasRep[0][wn * WN + j * 16],
                                       BN + 4, wmma::mem_row_major);
    } else if (ADD_INIT) {
        const float* ad = addend + (long)(z >> 4) * addBS;
#pragma unroll
        for (int i = 0; i < 2; i++) {
            int mm = m0 + wm * 32 + i * 16;
#pragma unroll
            for (int j = 0; j < NI; j++) {
                int nn = n0 + wn * WN + j * 16;
                wmma::load_matrix_sync(acc[i][j], ad + (long)mm * N + nn, N,
                                       wmma::mem_row_major);
            }
        }
    } else {
#pragma unroll
        for (int i = 0; i < 2; i++)
#pragma unroll
            for (int j = 0; j < NI; j++)
                wmma::fill_fragment(acc[i][j], 0.0f);
    }

    // Global load mapping: 32 rows per pass, 8 float4 per row.
    const int arow = tid >> 3;
    const int acol = (tid & 7) * 4;

    for (int kt = 0; kt < K; kt += BK) {
        __syncthreads();
#pragma unroll
        for (int r = 0; r < BM; r += 32) {
            float4 v = *(const float4*)(A + (long)(m0 + arow + r) * K + kt + acol);
            As[arow + r][acol + 0] = wmma::__float_to_tf32(v.x);
            As[arow + r][acol + 1] = wmma::__float_to_tf32(v.y);
            As[arow + r][acol + 2] = wmma::__float_to_tf32(v.z);
            As[arow + r][acol + 3] = wmma::__float_to_tf32(v.w);
        }
#pragma unroll
        for (int r = 0; r < BN; r += 32) {
            float4 v = *(const float4*)(B + (long)(n0 + arow + r) * K + kt + acol);
            Bs[arow + r][acol + 0] = wmma::__float_to_tf32(v.x);
            Bs[arow + r][acol + 1] = wmma::__float_to_tf32(v.y);
            Bs[arow + r][acol + 2] = wmma::__float_to_tf32(v.z);
            Bs[arow + r][acol + 3] = wmma::__float_to_tf32(v.w);
        }
        __syncthreads();
#pragma unroll
        for (int kk = 0; kk < BK; kk += 8) {
            wmma::fragment<wmma::matrix_a, 16, 16, 8, wmma::precision::tf32,
                           wmma::row_major> af[2];
            wmma::fragment<wmma::matrix_b, 16, 16, 8, wmma::precision::tf32,
                           wmma::col_major> bf[NI];
#pragma unroll
            for (int i = 0; i < 2; i++)
                wmma::load_matrix_sync(af[i], &As[wm * 32 + i * 16][kk], BK + 4);
#pragma unroll
            for (int j = 0; j < NI; j++)
                wmma::load_matrix_sync(bf[j], &Bs[wn * WN + j * 16][kk], BK + 4);
#pragma unroll
            for (int i = 0; i < 2; i++)
#pragma unroll
                for (int j = 0; j < NI; j++)
                    wmma::mma_sync(acc[i][j], af[i], bf[j], acc[i][j]);
        }
    }

    // Epilogue: every variant is a direct fragment store.
#pragma unroll
    for (int i = 0; i < 2; i++) {
        int mm = m0 + wm * 32 + i * 16;
#pragma unroll
        for (int j = 0; j < NI; j++) {
            int nn = n0 + wn * WN + j * 16;
            if (EPI == EPI_PLAIN) {
                wmma::store_matrix_sync(C + (long)z * cBS + (long)mm * N + nn,
                                        acc[i][j], N, wmma::mem_row_major);
            } else if (EPI == EPI_HEADS) {
                // (m=(b,l), n=(h,d)) -> dst[b,h,l,d], ld=64
                int b_ = mm >> 10, l_ = mm & 1023, h_ = nn >> 6, d_ = nn & 63;
                wmma::store_matrix_sync(
                    C + (((long)(b_ * NH + h_) << 10) + l_) * 64 + d_,
                    acc[i][j], 64, wmma::mem_row_major);
            } else if (EPI == EPI_HEADST) {
                // (m=(b,l), n=(h,d)) -> vt[b,h,d,l]: col-major store, ld=1024
                int b_ = mm >> 10, l_ = mm & 1023, h_ = nn >> 6, d_ = nn & 63;
                wmma::store_matrix_sync(
                    C + ((long)((b_ * NH + h_) * 64 + d_) << 10) + l_,
                    acc[i][j], 1024, wmma::mem_col_major);
            } else {  // EPI_X: z=(b,h); (m=q, n=d) -> x[b,q,h*64+d], ld=1024
                int b_ = z >> 4, h_ = z & 15;
                wmma::store_matrix_sync(
                    C + (((long)(b_ << 10) + mm) << 10) + h_ * 64 + nn,
                    acc[i][j], 1024, wmma::mem_row_major);
            }
        }
    }
}

// t_out[b*L+l, dt] = sum_k T[b*L+l,k]*WT[dt,k] + bT[dt]  (tiny)
__global__ void __launch_bounds__(256)
tproj(const float* __restrict__ T, const float* __restrict__ WT,
      const float* __restrict__ bT, float* __restrict__ t_out)
{
    __shared__ float Ws[64][65];
    __shared__ float Ts[4][64];
    int tid = threadIdx.x;
    for (int i = tid; i < 64 * 64; i += 256) Ws[i >> 6][i & 63] = WT[i];
    int r0 = blockIdx.x * 4;
    Ts[tid >> 6][tid & 63] = T[r0 * 64 + tid];
    __syncthreads();
    int lr = tid >> 6, dt = tid & 63;
    float s = bT[dt];
#pragma unroll
    for (int k2 = 0; k2 < 64; k2++) s += Ts[lr][k2] * Ws[dt][k2];
    t_out[(r0 + lr) * 64 + dt] = s;
}

// Pack mask (b,1,L,L) int32 -> 1 bit per element. One 32-col word per thread.
__global__ void __launch_bounds__(256)
mask_pack(const int* __restrict__ mask, unsigned* __restrict__ mp)
{
    long g = (long)blockIdx.x * 256 + threadIdx.x;
    const int4* src = (const int4*)(mask + g * 32);
    unsigned bits = 0;
#pragma unroll
    for (int i = 0; i < 8; i++) {
        int4 m = src[i];
        bits |= (unsigned)(m.x == 1) << (i * 4 + 0);
        bits |= (unsigned)(m.y == 1) << (i * 4 + 1);
        bits |= (unsigned)(m.z == 1) << (i * 4 + 2);
        bits |= (unsigned)(m.w == 1) << (i * 4 + 3);
    }
    mp[g] = bits;
}

// Row softmax with scale + packed mask (in place on S). 128 thr per row.
__global__ void __launch_bounds__(128)
softmax_kernel(float* __restrict__ S, const unsigned* __restrict__ mp)
{
    long r = blockIdx.x;                  // r = bh*1024 + q
    int q = (int)(r & 1023);
    int b = (int)(r >> 14);               // bh >> 4
    float* row = S + (r << 10);
    const unsigned* mrow = mp + ((((long)b) << 10) + q) * 32;
    int tid = threadIdx.x;
    int c0 = tid * 8;
    float4 s0 = *(const float4*)(row + c0);
    float4 s1 = *(const float4*)(row + c0 + 4);
    unsigned mb = (mrow[tid >> 2] >> ((tid & 3) * 8)) & 0xffu;
    const float sc = 0.08838834764831845f;  // 1/sqrt(128)
    float v[8];
    v[0] = (mb & 1u)   ? -1e9f : s0.x * sc;
    v[1] = (mb & 2u)   ? -1e9f : s0.y * sc;
    v[2] = (mb & 4u)   ? -1e9f : s0.z * sc;
    v[3] = (mb & 8u)   ? -1e9f : s0.w * sc;
    v[4] = (mb & 16u)  ? -1e9f : s1.x * sc;
    v[5] = (mb & 32u)  ? -1e9f : s1.y * sc;
    v[6] = (mb & 64u)  ? -1e9f : s1.z * sc;
    v[7] = (mb & 128u) ? -1e9f : s1.w * sc;

    float mx = v[0];
#pragma unroll
    for (int i = 1; i < 8; i++) mx = fmaxf(mx, v[i]);
#pragma unroll
    for (int o = 16; o; o >>= 1) mx = fmaxf(mx, __shfl_xor_sync(0xffffffffu, mx, o));
    __shared__ float sm_[4], ss_[4];
    int lane = tid & 31, w = tid >> 5;
    if (lane == 0) sm_[w] = mx;
    __syncthreads();
    mx = fmaxf(fmaxf(sm_[0], sm_[1]), fmaxf(sm_[2], sm_[3]));

    float e[8];
    float sum = 0.f;
#pragma unroll
    for (int i = 0; i < 8; i++) { e[i] = __expf(v[i] - mx); sum += e[i]; }
#pragma unroll
    for (int o = 16; o; o >>= 1) sum += __shfl_xor_sync(0xffffffffu, sum, o);
    if (lane == 0) ss_[w] = sum;
    __syncthreads();
    sum = ss_[0] + ss_[1] + ss_[2] + ss_[3];
    float inv = 1.0f / sum;
    *(float4*)(row + c0)     = make_float4(e[0] * inv, e[1] * inv, e[2] * inv, e[3] * inv);
    *(float4*)(row + c0 + 4) = make_float4(e[4] * inv, e[5] * inv, e[6] * inv, e[7] * inv);
}

static float* symaddr(const void* sym)
{
    void* p = nullptr;
    cudaGetSymbolAddress(&p, sym);
    return (float*)p;
}

extern "C" void kernel_launch(void* const* d_in, const int* in_sizes, int n_in,
                              void* d_out, int out_size)
{
    const float* Qin  = (const float*)d_in[0];
    const float* Kin  = (const float*)d_in[1];
    const float* Vin  = (const float*)d_in[2];
    const float* Tin  = (const float*)d_in[3];
    const int*   mask = (const int*)d_in[4];
    const float* WQ = (const float*)d_in[5];
    const float* bQ = (const float*)d_in[6];
    const float* WK = (const float*)d_in[7];
    const float* bK = (const float*)d_in[8];
    const float* WV = (const float*)d_in[9];
    const float* bV = (const float*)d_in[10];
    const float* WM = (const float*)d_in[11];
    const float* bM = (const float*)d_in[12];
    const float* WT = (const float*)d_in[13];
    const float* bT = (const float*)d_in[14];
    float* out = (float*)d_out;

    float* q  = symaddr(g_q);
    float* k  = symaddr(g_k);
    float* vt = symaddr(g_vt);
    float* t  = symaddr(g_t);
    float* TT = symaddr(g_TT);
    float* S  = symaddr(g_S);
    float* x  = symaddr(g_x);
    unsigned* mp = (unsigned*)symaddr(g_mp);

    const int M = BB * LL;  // 8192
    dim3 gProj(DM / 128, M / 128, 1);  // (8, 64)

    // Pack mask early (independent).
    mask_pack<<<BB * LL * (LL / 32) / 256, 256>>>(mask, mp);

    // 1-3: Q/K/V projections (tf32). q,k head-split; v head-split + transposed.
    wgemm<128, 64, EPI_HEADS,  true, false><<<gProj, 256>>>(
        Qin, WQ, bQ, nullptr, q, M, DM, DM, 0, 0, 0, 0);
    wgemm<128, 64, EPI_HEADS,  true, false><<<gProj, 256>>>(
        Kin, WK, bK, nullptr, k, M, DM, DM, 0, 0, 0, 0);
    wgemm<128, 64, EPI_HEADST, true, false><<<gProj, 256>>>(
        Vin, WV, bV, nullptr, vt, M, DM, DM, 0, 0, 0, 0);

    // 4: temporal projection t = T @ WT.T + bT
    tproj<<<M / 4, 256>>>(Tin, WT, bT, t);

    // 5: TT[b,q,k] = t[b,q,:].t[b,k,:]  (shared across all 16 heads)
    wgemm<128, 64, EPI_PLAIN, false, false><<<dim3(8, 8, BB), 256>>>(
        t, t, nullptr, nullptr, TT, LL, LL, DTT,
        (long)LL * DTT, (long)LL * DTT, (long)LL * LL, 0);

    // 6: S[bh,q,k] = q.k (64-dim) + TT[b,q,k]  (TT loaded as initial accumulator)
    wgemm<128, 64, EPI_PLAIN, false, true><<<dim3(8, 8, BB * NH), 256>>>(
        q, k, nullptr, TT, S, LL, LL, DV,
        (long)LL * DV, (long)LL * DV, (long)LL * LL, (long)LL * LL);

    // 7: scale + mask + softmax, in place
    softmax_kernel<<<BB * NH * LL, 128>>>(S, mp);

    // 8: x[b,q,h*64+d] = P @ Vt^T  (NT, N=64)
    wgemm<64, 32, EPI_X, false, false><<<dim3(1, 8, BB * NH), 256>>>(
        S, vt, nullptr, nullptr, x, LL, DV, LL,
        (long)LL * LL, (long)DV * LL, 0, 0);

    // 9: out = x @ WM.T + bM
    wgemm<128, 64, EPI_PLAIN, true, false><<<gProj, 256>>>(
        x, WM, bM, nullptr, out, M, DM, DM, 0, 0, 0, 0);
}

// round 8
// speedup vs baseline: 1.5425x; 1.2015x over previous
#include <cuda_runtime.h>
#include <mma.h>
using namespace nvcuda;

// Problem constants
#define BB 8
#define LL 1024
#define DM 1024
#define NH 16
#define DV 64
#define DTT 64

// Scratch (device globals: allocation-free contract)
__device__ float g_q[BB * NH * LL * DV];            // 32 MB  (b,h,l,64)
__device__ float g_k[BB * NH * LL * DV];            // 32 MB
__device__ float g_vt[BB * NH * DV * LL];           // 32 MB  (b,h,d,l)  V transposed
__device__ float g_t[BB * LL * DTT];                // 2 MB
__device__ float g_TT[BB * LL * LL];                // 32 MB  (b,q,k) t.t' shared across heads
__device__ float g_S[(size_t)BB * NH * LL * LL];    // 512 MB (bh,q,k)
__device__ float g_x[BB * LL * DM];                 // 32 MB
__device__ unsigned g_mp[BB * LL * (LL / 32)];      // 1 MB packed mask bits

enum { EPI_PLAIN = 0, EPI_HEADS = 1, EPI_HEADST = 2, EPI_X = 3 };

__device__ __forceinline__ unsigned smem_u32(const void* p)
{
    return (unsigned)__cvta_generic_to_shared(p);
}
#define CP16(dst, src) \
    asm volatile("cp.async.cg.shared.global [%0], [%1], 16;" ::"r"(dst), "l"(src))
#define CP_COMMIT() asm volatile("cp.async.commit_group;")
#define CP_WAIT1() asm volatile("cp.async.wait_group 1;")
#define CP_WAIT0() asm volatile("cp.async.wait_group 0;")

// C[m,n] = sum_k A[m,k]*B[n,k]  (NT) tf32 tensor cores, cp.async double-buffered.
// BM=128, BK=32, 256 threads = 8 warps as 2(m) x 4(n); warp tile 64 x WN.
// smem (dynamic): As[2][128][36] ++ Bs[2][BN][36].
template <int BN, int WN, int EPI, bool HAS_BIAS, bool ADD_INIT>
__global__ void __launch_bounds__(256, 2)
wgemm(const float* __restrict__ A, const float* __restrict__ B,
      const float* __restrict__ bias, const float* __restrict__ addend,
      float* __restrict__ C, int M, int N, int K,
      long aBS, long bBS, long cBS, long addBS)
{
    constexpr int BM = 128, BK = 32, LDS_ = BK + 4;
    constexpr int WM = 64;
    constexpr int MI = WM / 16;   // 4
    constexpr int NI = WN / 16;   // 2 (BN=128) or 1 (BN=64)
    static_assert((BM / WM) * (BN / WN) == 8, "8 warps");

    extern __shared__ float smem[];
    float* AS = smem;                       // [2][BM][LDS_]
    float* BS = smem + 2 * BM * LDS_;       // [2][BN][LDS_]

    const int z = blockIdx.z;
    A += (long)z * aBS;
    B += (long)z * bBS;
    const int m0 = blockIdx.y * BM;
    const int n0 = blockIdx.x * BN;
    const int tid = threadIdx.x;
    const int w = tid >> 5;
    const int wm = w >> 2;   // 0..1
    const int wn = w & 3;    // 0..3

    wmma::fragment<wmma::accumulator, 16, 16, 8, float> acc[MI][NI];

    if (HAS_BIAS) {
        // Replicate bias over 16 rows, load as initial accumulator.
        for (int i = tid; i < 16 * BN; i += 256)
            smem[(i / BN) * (BN + 4) + (i % BN)] = bias[n0 + (i % BN)];
        __syncthreads();
#pragma unroll
        for (int i = 0; i < MI; i++)
#pragma unroll
            for (int j = 0; j < NI; j++)
                wmma::load_matrix_sync(acc[i][j], &smem[wn * WN + j * 16],
                                       BN + 4, wmma::mem_row_major);
        __syncthreads();
    } else if (ADD_INIT) {
        const float* ad = addend + (long)(z >> 4) * addBS;
#pragma unroll
        for (int i = 0; i < MI; i++) {
            int mm = m0 + wm * WM + i * 16;
#pragma unroll
            for (int j = 0; j < NI; j++) {
                int nn = n0 + wn * WN + j * 16;
                wmma::load_matrix_sync(acc[i][j], ad + (long)mm * N + nn, N,
                                       wmma::mem_row_major);
            }
        }
    } else {
#pragma unroll
        for (int i = 0; i < MI; i++)
#pragma unroll
            for (int j = 0; j < NI; j++)
                wmma::fill_fragment(acc[i][j], 0.0f);
    }

    // Tile loader: 256 threads, 16B per cp.async. row = tid>>3 (+32 steps).
    const int ldrow = tid >> 3;
    const int ldcol = (tid & 7) << 2;
    const float* Ald = A + (long)(m0 + ldrow) * K + ldcol;
    const float* Bld = B + (long)(n0 + ldrow) * K + ldcol;

    const int ntiles = K / BK;

    auto load_tile = [&](int st, int t) {
        const int kt = t * BK;
        float* as = AS + (st * BM + ldrow) * LDS_ + ldcol;
        float* bs = BS + (st * BN + ldrow) * LDS_ + ldcol;
#pragma unroll
        for (int r = 0; r < BM; r += 32)
            CP16(smem_u32(as + r * LDS_), Ald + (long)r * K + kt);
#pragma unroll
        for (int r = 0; r < BN; r += 32)
            CP16(smem_u32(bs + r * LDS_), Bld + (long)r * K + kt);
    };

    load_tile(0, 0);
    CP_COMMIT();

    for (int t = 0; t < ntiles; ++t) {
        const int cur = t & 1;
        if (t + 1 < ntiles) {
            load_tile(1 - cur, t + 1);
            CP_COMMIT();
            CP_WAIT1();
        } else {
            CP_WAIT0();
        }
        __syncthreads();

        const float* asBase = AS + (cur * BM + wm * WM) * LDS_;
        const float* bsBase = BS + (cur * BN + wn * WN) * LDS_;
#pragma unroll
        for (int kk = 0; kk < BK; kk += 8) {
            wmma::fragment<wmma::matrix_a, 16, 16, 8, wmma::precision::tf32,
                           wmma::row_major> af[MI];
            wmma::fragment<wmma::matrix_b, 16, 16, 8, wmma::precision::tf32,
                           wmma::col_major> bf[NI];
#pragma unroll
            for (int i = 0; i < MI; i++) {
                wmma::load_matrix_sync(af[i], asBase + i * 16 * LDS_ + kk, LDS_);
#pragma unroll
                for (int e = 0; e < af[i].num_elements; e++)
                    af[i].x[e] = wmma::__float_to_tf32(af[i].x[e]);
            }
#pragma unroll
            for (int j = 0; j < NI; j++) {
                wmma::load_matrix_sync(bf[j], bsBase + j * 16 * LDS_ + kk, LDS_);
#pragma unroll
                for (int e = 0; e < bf[j].num_elements; e++)
                    bf[j].x[e] = wmma::__float_to_tf32(bf[j].x[e]);
            }
#pragma unroll
            for (int i = 0; i < MI; i++)
#pragma unroll
                for (int j = 0; j < NI; j++)
                    wmma::mma_sync(acc[i][j], af[i], bf[j], acc[i][j]);
        }
        __syncthreads();
    }

    // Epilogue: direct fragment stores.
#pragma unroll
    for (int i = 0; i < MI; i++) {
        int mm = m0 + wm * WM + i * 16;
#pragma unroll
        for (int j = 0; j < NI; j++) {
            int nn = n0 + wn * WN + j * 16;
            if (EPI == EPI_PLAIN) {
                wmma::store_matrix_sync(C + (long)z * cBS + (long)mm * N + nn,
                                        acc[i][j], N, wmma::mem_row_major);
            } else if (EPI == EPI_HEADS) {
                // (m=(b,l), n=(h,d)) -> dst[b,h,l,d], ld=64
                int b_ = mm >> 10, l_ = mm & 1023, h_ = nn >> 6, d_ = nn & 63;
                wmma::store_matrix_sync(
                    C + (((long)(b_ * NH + h_) << 10) + l_) * 64 + d_,
                    acc[i][j], 64, wmma::mem_row_major);
            } else if (EPI == EPI_HEADST) {
                // (m=(b,l), n=(h,d)) -> vt[b,h,d,l]: col-major store, ld=1024
                int b_ = mm >> 10, l_ = mm & 1023, h_ = nn >> 6, d_ = nn & 63;
                wmma::store_matrix_sync(
                    C + ((long)((b_ * NH + h_) * 64 + d_) << 10) + l_,
                    acc[i][j], 1024, wmma::mem_col_major);
            } else {  // EPI_X: z=(b,h); (m=q, n=d) -> x[b,q,h*64+d], ld=1024
                int b_ = z >> 4, h_ = z & 15;
                wmma::store_matrix_sync(
                    C + (((long)(b_ << 10) + mm) << 10) + h_ * 64 + nn,
                    acc[i][j], 1024, wmma::mem_row_major);
            }
        }
    }
}

// t_out[b*L+l, dt] = sum_k T[b*L+l,k]*WT[dt,k] + bT[dt]  (tiny)
__global__ void __launch_bounds__(256)
tproj(const float* __restrict__ T, const float* __restrict__ WT,
      const float* __restrict__ bT, float* __restrict__ t_out)
{
    __shared__ float Ws[64][65];
    __shared__ float Ts[4][64];
    int tid = threadIdx.x;
    for (int i = tid; i < 64 * 64; i += 256) Ws[i >> 6][i & 63] = WT[i];
    int r0 = blockIdx.x * 4;
    Ts[tid >> 6][tid & 63] = T[r0 * 64 + tid];
    __syncthreads();
    int lr = tid >> 6, dt = tid & 63;
    float s = bT[dt];
#pragma unroll
    for (int k2 = 0; k2 < 64; k2++) s += Ts[lr][k2] * Ws[dt][k2];
    t_out[(r0 + lr) * 64 + dt] = s;
}

// Pack mask (b,1,L,L) int32 -> 1 bit per element. One 32-col word per thread.
__global__ void __launch_bounds__(256)
mask_pack(const int* __restrict__ mask, unsigned* __restrict__ mp)
{
    long g = (long)blockIdx.x * 256 + threadIdx.x;
    const int4* src = (const int4*)(mask + g * 32);
    unsigned bits = 0;
#pragma unroll
    for (int i = 0; i < 8; i++) {
        int4 m = src[i];
        bits |= (unsigned)(m.x == 1) << (i * 4 + 0);
        bits |= (unsigned)(m.y == 1) << (i * 4 + 1);
        bits |= (unsigned)(m.z == 1) << (i * 4 + 2);
        bits |= (unsigned)(m.w == 1) << (i * 4 + 3);
    }
    mp[g] = bits;
}

// Row softmax with scale + packed mask (in place on S). 128 thr per row.
__global__ void __launch_bounds__(128)
softmax_kernel(float* __restrict__ S, const unsigned* __restrict__ mp)
{
    long r = blockIdx.x;                  // r = bh*1024 + q
    int q = (int)(r & 1023);
    int b = (int)(r >> 14);               // bh >> 4
    float* row = S + (r << 10);
    const unsigned* mrow = mp + ((((long)b) << 10) + q) * 32;
    int tid = threadIdx.x;
    int c0 = tid * 8;
    float4 s0 = *(const float4*)(row + c0);
    float4 s1 = *(const float4*)(row + c0 + 4);
    unsigned mb = (mrow[tid >> 2] >> ((tid & 3) * 8)) & 0xffu;
    const float sc = 0.08838834764831845f;  // 1/sqrt(128)
    float v[8];
    v[0] = (mb & 1u)   ? -1e9f : s0.x * sc;
    v[1] = (mb & 2u)   ? -1e9f : s0.y * sc;
    v[2] = (mb & 4u)   ? -1e9f : s0.z * sc;
    v[3] = (mb & 8u)   ? -1e9f : s0.w * sc;
    v[4] = (mb & 16u)  ? -1e9f : s1.x * sc;
    v[5] = (mb & 32u)  ? -1e9f : s1.y * sc;
    v[6] = (mb & 64u)  ? -1e9f : s1.z * sc;
    v[7] = (mb & 128u) ? -1e9f : s1.w * sc;

    float mx = v[0];
#pragma unroll
    for (int i = 1; i < 8; i++) mx = fmaxf(mx, v[i]);
#pragma unroll
    for (int o = 16; o; o >>= 1) mx = fmaxf(mx, __shfl_xor_sync(0xffffffffu, mx, o));
    __shared__ float sm_[4], ss_[4];
    int lane = tid & 31, w = tid >> 5;
    if (lane == 0) sm_[w] = mx;
    __syncthreads();
    mx = fmaxf(fmaxf(sm_[0], sm_[1]), fmaxf(sm_[2], sm_[3]));

    float e[8];
    float sum = 0.f;
#pragma unroll
    for (int i = 0; i < 8; i++) { e[i] = __expf(v[i] - mx); sum += e[i]; }
#pragma unroll
    for (int o = 16; o; o >>= 1) sum += __shfl_xor_sync(0xffffffffu, sum, o);
    if (lane == 0) ss_[w] = sum;
    __syncthreads();
    sum = ss_[0] + ss_[1] + ss_[2] + ss_[3];
    float inv = 1.0f / sum;
    *(float4*)(row + c0)     = make_float4(e[0] * inv, e[1] * inv, e[2] * inv, e[3] * inv);
    *(float4*)(row + c0 + 4) = make_float4(e[4] * inv, e[5] * inv, e[6] * inv, e[7] * inv);
}

static float* symaddr(const void* sym)
{
    void* p = nullptr;
    cudaGetSymbolAddress(&p, sym);
    return (float*)p;
}

// Dynamic smem: 2*(128+BN)*36 floats
static constexpr int smemBytes(int BN) { return 2 * (128 + BN) * 36 * 4; }

extern "C" void kernel_launch(void* const* d_in, const int* in_sizes, int n_in,
                              void* d_out, int out_size)
{
    const float* Qin  = (const float*)d_in[0];
    const float* Kin  = (const float*)d_in[1];
    const float* Vin  = (const float*)d_in[2];
    const float* Tin  = (const float*)d_in[3];
    const int*   mask = (const int*)d_in[4];
    const float* WQ = (const float*)d_in[5];
    const float* bQ = (const float*)d_in[6];
    const float* WK = (const float*)d_in[7];
    const float* bK = (const float*)d_in[8];
    const float* WV = (const float*)d_in[9];
    const float* bV = (const float*)d_in[10];
    const float* WM = (const float*)d_in[11];
    const float* bM = (const float*)d_in[12];
    const float* WT = (const float*)d_in[13];
    const float* bT = (const float*)d_in[14];
    float* out = (float*)d_out;

    float* q  = symaddr(g_q);
    float* k  = symaddr(g_k);
    float* vt = symaddr(g_vt);
    float* t  = symaddr(g_t);
    float* TT = symaddr(g_TT);
    float* S  = symaddr(g_S);
    float* x  = symaddr(g_x);
    unsigned* mp = (unsigned*)symaddr(g_mp);

    const int M = BB * LL;  // 8192
    dim3 gProj(DM / 128, M / 128, 1);  // (8, 64)
    const int SM128 = smemBytes(128);
    const int SM64  = smemBytes(64);

    // Opt-in to >48KB dynamic smem (idempotent; capture-safe host config).
    static int attrDone = 0;
    if (!attrDone) {
        cudaFuncSetAttribute(wgemm<128, 32, EPI_HEADS,  true,  false>,
                             cudaFuncAttributeMaxDynamicSharedMemorySize, SM128);
        cudaFuncSetAttribute(wgemm<128, 32, EPI_HEADST, true,  false>,
                             cudaFuncAttributeMaxDynamicSharedMemorySize, SM128);
        cudaFuncSetAttribute(wgemm<128, 32, EPI_PLAIN,  false, false>,
                             cudaFuncAttributeMaxDynamicSharedMemorySize, SM128);
        cudaFuncSetAttribute(wgemm<128, 32, EPI_PLAIN,  false, true>,
                             cudaFuncAttributeMaxDynamicSharedMemorySize, SM128);
        cudaFuncSetAttribute(wgemm<128, 32, EPI_PLAIN,  true,  false>,
                             cudaFuncAttributeMaxDynamicSharedMemorySize, SM128);
        cudaFuncSetAttribute(wgemm<64, 16, EPI_X, false, false>,
                             cudaFuncAttributeMaxDynamicSharedMemorySize, SM64);
        attrDone = 1;
    }

    // Pack mask early (independent).
    mask_pack<<<BB * LL * (LL / 32) / 256, 256>>>(mask, mp);

    // 1-3: Q/K/V projections (tf32). q,k head-split; v head-split + transposed.
    wgemm<128, 32, EPI_HEADS, true, false><<<gProj, 256, SM128>>>(
        Qin, WQ, bQ, nullptr, q, M, DM, DM, 0, 0, 0, 0);
    wgemm<128, 32, EPI_HEADS, true, false><<<gProj, 256, SM128>>>(
        Kin, WK, bK, nullptr, k, M, DM, DM, 0, 0, 0, 0);
    wgemm<128, 32, EPI_HEADST, true, false><<<gProj, 256, SM128>>>(
        Vin, WV, bV, nullptr, vt, M, DM, DM, 0, 0, 0, 0);

    // 4: temporal projection t = T @ WT.T + bT
    tproj<<<M / 4, 256>>>(Tin, WT, bT, t);

    // 5: TT[b,q,k] = t[b,q,:].t[b,k,:]  (shared across all 16 heads)
    wgemm<128, 32, EPI_PLAIN, false, false><<<dim3(8, 8, BB), 256, SM128>>>(
        t, t, nullptr, nullptr, TT, LL, LL, DTT,
        (long)LL * DTT, (long)LL * DTT, (long)LL * LL, 0);

    // 6: S[bh,q,k] = q.k (64-dim) + TT[b,q,k]  (TT loaded as initial accumulator)
    wgemm<128, 32, EPI_PLAIN, false, true><<<dim3(8, 8, BB * NH), 256, SM128>>>(
        q, k, nullptr, TT, S, LL, LL, DV,
        (long)LL * DV, (long)LL * DV, (long)LL * LL, (long)LL * LL);

    // 7: scale + mask + softmax, in place
    softmax_kernel<<<BB * NH * LL, 128>>>(S, mp);

    // 8: x[b,q,h*64+d] = P @ Vt^T  (NT, N=64)
    wgemm<64, 16, EPI_X, false, false><<<dim3(1, 8, BB * NH), 256, SM64>>>(
        S, vt, nullptr, nullptr, x, LL, DV, LL,
        (long)LL * LL, (long)DV * LL, 0, 0);

    // 9: out = x @ WM.T + bM
    wgemm<128, 32, EPI_PLAIN, true, false><<<gProj, 256, SM128>>>(
        x, WM, bM, nullptr, out, M, DM, DM, 0, 0, 0, 0);
}

// round 9
// speedup vs baseline: 1.5980x; 1.0360x over previous
#include <cuda_runtime.h>
#include <mma.h>
using namespace nvcuda;

// Problem constants
#define BB 8
#define LL 1024
#define DM 1024
#define NH 16
#define DV 64
#define DTT 64

// Scratch (device globals: allocation-free contract)
__device__ float g_q[BB * NH * LL * DV];            // 32 MB  (b,h,l,64)  tf32-rounded
__device__ float g_k[BB * NH * LL * DV];            // 32 MB  tf32-rounded
__device__ float g_vt[BB * NH * DV * LL];           // 32 MB  (b,h,d,l)  V^T, tf32-rounded
__device__ float g_t[BB * LL * DTT];                // 2 MB   tf32-rounded
__device__ float g_TT[BB * LL * LL];                // 32 MB  (b,q,k) t.t' shared across heads
__device__ float g_S[(size_t)BB * NH * LL * LL];    // 512 MB (bh,q,k)
__device__ float g_x[BB * LL * DM];                 // 32 MB  tf32-rounded
__device__ unsigned g_mp[BB * LL * (LL / 32)];      // 1 MB packed mask bits
__device__ float g_rQ[BB * LL * DM];                // 32 MB tf32-rounded input copies
__device__ float g_rK[BB * LL * DM];
__device__ float g_rV[BB * LL * DM];
__device__ float g_rW[4 * DM * DM];                 // 16 MB: WQ,WK,WV,WM rounded

enum { EPI_PLAIN = 0, EPI_HEADS = 1, EPI_HEADST = 2, EPI_X = 3 };

__device__ __forceinline__ float to_tf32(float x)
{
    float y;
    asm("cvt.rna.tf32.f32 %0, %1;" : "=f"(y) : "f"(x));
    return y;
}

__device__ __forceinline__ unsigned smem_u32(const void* p)
{
    return (unsigned)__cvta_generic_to_shared(p);
}
#define CP16(dst, src) \
    asm volatile("cp.async.cg.shared.global [%0], [%1], 16;" ::"r"(dst), "l"(src))
#define CP_COMMIT() asm volatile("cp.async.commit_group;")
#define CP_WAIT1() asm volatile("cp.async.wait_group 1;")
#define CP_WAIT0() asm volatile("cp.async.wait_group 0;")

// C[m,n] = sum_k A[m,k]*B[n,k] (NT) tf32 tensor cores, 3-stage cp.async ring,
// ONE __syncthreads per K-tile. All operands pre-rounded to tf32 (no cvt in loop).
// BM=128, BK=32, 256 threads = 8 warps as 2(m) x 4(n); warp tile 64 x WN.
template <int BN, int WN, int EPI, bool HAS_BIAS, bool ADD_INIT, bool CVT_OUT>
__global__ void __launch_bounds__(256, 2)
wgemm(const float* __restrict__ A, const float* __restrict__ B,
      const float* __restrict__ bias, const float* __restrict__ addend,
      float* __restrict__ C, int M, int N, int K,
      long aBS, long bBS, long cBS, long addBS)
{
    constexpr int BM = 128, BK = 32, LDS_ = BK + 4;
    constexpr int WM = 64;
    constexpr int MI = WM / 16;   // 4
    constexpr int NI = WN / 16;   // 2 (BN=128) or 1 (BN=64)
    static_assert((BM / WM) * (BN / WN) == 8, "8 warps");

    extern __shared__ float smem[];
    float* AS = smem;                        // [3][BM][LDS_]
    float* BS = smem + 3 * BM * LDS_;        // [3][BN][LDS_]

    const int z = blockIdx.z;
    A += (long)z * aBS;
    B += (long)z * bBS;
    const int m0 = blockIdx.y * BM;
    const int n0 = blockIdx.x * BN;
    const int tid = threadIdx.x;
    const int w = tid >> 5;
    const int wm = w >> 2;   // 0..1
    const int wn = w & 3;    // 0..3

    wmma::fragment<wmma::accumulator, 16, 16, 8, float> acc[MI][NI];

    if (HAS_BIAS) {
        for (int i = tid; i < 16 * BN; i += 256)
            smem[(i / BN) * (BN + 4) + (i % BN)] = bias[n0 + (i % BN)];
        __syncthreads();
#pragma unroll
        for (int i = 0; i < MI; i++)
#pragma unroll
            for (int j = 0; j < NI; j++)
                wmma::load_matrix_sync(acc[i][j], &smem[wn * WN + j * 16],
                                       BN + 4, wmma::mem_row_major);
        __syncthreads();
    } else if (ADD_INIT) {
        const float* ad = addend + (long)(z >> 4) * addBS;
#pragma unroll
        for (int i = 0; i < MI; i++) {
            int mm = m0 + wm * WM + i * 16;
#pragma unroll
            for (int j = 0; j < NI; j++) {
                int nn = n0 + wn * WN + j * 16;
                wmma::load_matrix_sync(acc[i][j], ad + (long)mm * N + nn, N,
                                       wmma::mem_row_major);
            }
        }
    } else {
#pragma unroll
        for (int i = 0; i < MI; i++)
#pragma unroll
            for (int j = 0; j < NI; j++)
                wmma::fill_fragment(acc[i][j], 0.0f);
    }

    // Tile loader: 256 threads, 16B per cp.async.
    const int ldrow = tid >> 3;
    const int ldcol = (tid & 7) << 2;
    const float* Ald = A + (long)(m0 + ldrow) * K + ldcol;
    const float* Bld = B + (long)(n0 + ldrow) * K + ldcol;

    const int ntiles = K / BK;

    auto load_tile = [&](int st, int t) {
        const int kt = t * BK;
        float* as = AS + (st * BM + ldrow) * LDS_ + ldcol;
        float* bs = BS + (st * BN + ldrow) * LDS_ + ldcol;
#pragma unroll
        for (int r = 0; r < BM; r += 32)
            CP16(smem_u32(as + r * LDS_), Ald + (long)r * K + kt);
#pragma unroll
        for (int r = 0; r < BN; r += 32)
            CP16(smem_u32(bs + r * LDS_), Bld + (long)r * K + kt);
    };

    load_tile(0, 0);
    CP_COMMIT();
    if (ntiles > 1) {
        load_tile(1, 1);
        CP_COMMIT();
    }

    for (int t = 0; t < ntiles; ++t) {
        if (t < ntiles - 1) CP_WAIT1(); else CP_WAIT0();
        __syncthreads();   // tile t visible; all compute(t-1) finished

        if (t + 2 < ntiles) {   // prefetch into buffer (t+2)%3 == (t-1)%3 (safe)
            load_tile((t + 2) % 3, t + 2);
            CP_COMMIT();
        }

        const int cur = t % 3;
        const float* asBase = AS + (cur * BM + wm * WM) * LDS_;
        const float* bsBase = BS + (cur * BN + wn * WN) * LDS_;
#pragma unroll
        for (int kk = 0; kk < BK; kk += 8) {
            wmma::fragment<wmma::matrix_a, 16, 16, 8, wmma::precision::tf32,
                           wmma::row_major> af[MI];
            wmma::fragment<wmma::matrix_b, 16, 16, 8, wmma::precision::tf32,
                           wmma::col_major> bf[NI];
#pragma unroll
            for (int i = 0; i < MI; i++)
                wmma::load_matrix_sync(af[i], asBase + i * 16 * LDS_ + kk, LDS_);
#pragma unroll
            for (int j = 0; j < NI; j++)
                wmma::load_matrix_sync(bf[j], bsBase + j * 16 * LDS_ + kk, LDS_);
#pragma unroll
            for (int i = 0; i < MI; i++)
#pragma unroll
                for (int j = 0; j < NI; j++)
                    wmma::mma_sync(acc[i][j], af[i], bf[j], acc[i][j]);
        }
    }

    // Optional output rounding (producers of tf32 operands for later stages)
    if (CVT_OUT) {
#pragma unroll
        for (int i = 0; i < MI; i++)
#pragma unroll
            for (int j = 0; j < NI; j++)
#pragma unroll
                for (int e = 0; e < acc[i][j].num_elements; e++)
                    acc[i][j].x[e] = to_tf32(acc[i][j].x[e]);
    }

    // Epilogue: direct fragment stores.
#pragma unroll
    for (int i = 0; i < MI; i++) {
        int mm = m0 + wm * WM + i * 16;
#pragma unroll
        for (int j = 0; j < NI; j++) {
            int nn = n0 + wn * WN + j * 16;
            if (EPI == EPI_PLAIN) {
                wmma::store_matrix_sync(C + (long)z * cBS + (long)mm * N + nn,
                                        acc[i][j], N, wmma::mem_row_major);
            } else if (EPI == EPI_HEADS) {
                int b_ = mm >> 10, l_ = mm & 1023, h_ = nn >> 6, d_ = nn & 63;
                wmma::store_matrix_sync(
                    C + (((long)(b_ * NH + h_) << 10) + l_) * 64 + d_,
                    acc[i][j], 64, wmma::mem_row_major);
            } else if (EPI == EPI_HEADST) {
                int b_ = mm >> 10, l_ = mm & 1023, h_ = nn >> 6, d_ = nn & 63;
                wmma::store_matrix_sync(
                    C + ((long)((b_ * NH + h_) * 64 + d_) << 10) + l_,
                    acc[i][j], 1024, wmma::mem_col_major);
            } else {  // EPI_X
                int b_ = z >> 4, h_ = z & 15;
                wmma::store_matrix_sync(
                    C + (((long)(b_ << 10) + mm) << 10) + h_ * 64 + nn,
                    acc[i][j], 1024, wmma::mem_row_major);
            }
        }
    }
}

// Elementwise tf32 rounding pass (float4 vectorized): out[i] = rna_tf32(in[i])
__global__ void __launch_bounds__(256)
round_pass(const float* __restrict__ in, float* __restrict__ out)
{
    int i = blockIdx.x * 256 + threadIdx.x;
    float4 v = ((const float4*)in)[i];
    v.x = to_tf32(v.x);
    v.y = to_tf32(v.y);
    v.z = to_tf32(v.z);
    v.w = to_tf32(v.w);
    ((float4*)out)[i] = v;
}

// t_out[b*L+l, dt] = sum_k T[b*L+l,k]*WT[dt,k] + bT[dt]  (tiny), tf32-rounded out
__global__ void __launch_bounds__(256)
tproj(const float* __restrict__ T, const float* __restrict__ WT,
      const float* __restrict__ bT, float* __restrict__ t_out)
{
    __shared__ float Ws[64][65];
    __shared__ float Ts[4][64];
    int tid = threadIdx.x;
    for (int i = tid; i < 64 * 64; i += 256) Ws[i >> 6][i & 63] = WT[i];
    int r0 = blockIdx.x * 4;
    Ts[tid >> 6][tid & 63] = T[r0 * 64 + tid];
    __syncthreads();
    int lr = tid >> 6, dt = tid & 63;
    float s = bT[dt];
#pragma unroll
    for (int k2 = 0; k2 < 64; k2++) s += Ts[lr][k2] * Ws[dt][k2];
    t_out[(r0 + lr) * 64 + dt] = to_tf32(s);
}

// Pack mask (b,1,L,L) int32 -> 1 bit per element.
__global__ void __launch_bounds__(256)
mask_pack(const int* __restrict__ mask, unsigned* __restrict__ mp)
{
    long g = (long)blockIdx.x * 256 + threadIdx.x;
    const int4* src = (const int4*)(mask + g * 32);
    unsigned bits = 0;
#pragma unroll
    for (int i = 0; i < 8; i++) {
        int4 m = src[i];
        bits |= (unsigned)(m.x == 1) << (i * 4 + 0);
        bits |= (unsigned)(m.y == 1) << (i * 4 + 1);
        bits |= (unsigned)(m.z == 1) << (i * 4 + 2);
        bits |= (unsigned)(m.w == 1) << (i * 4 + 3);
    }
    mp[g] = bits;
}

// Row softmax with scale + packed mask (in place on S); P rounded to tf32.
__global__ void __launch_bounds__(128)
softmax_kernel(float* __restrict__ S, const unsigned* __restrict__ mp)
{
    long r = blockIdx.x;                  // r = bh*1024 + q
    int q = (int)(r & 1023);
    int b = (int)(r >> 14);               // bh >> 4
    float* row = S + (r << 10);
    const unsigned* mrow = mp + ((((long)b) << 10) + q) * 32;
    int tid = threadIdx.x;
    int c0 = tid * 8;
    float4 s0 = *(const float4*)(row + c0);
    float4 s1 = *(const float4*)(row + c0 + 4);
    unsigned mb = (mrow[tid >> 2] >> ((tid & 3) * 8)) & 0xffu;
    const float sc = 0.08838834764831845f;  // 1/sqrt(128)
    float v[8];
    v[0] = (mb & 1u)   ? -1e9f : s0.x * sc;
    v[1] = (mb & 2u)   ? -1e9f : s0.y * sc;
    v[2] = (mb & 4u)   ? -1e9f : s0.z * sc;
    v[3] = (mb & 8u)   ? -1e9f : s0.w * sc;
    v[4] = (mb & 16u)  ? -1e9f : s1.x * sc;
    v[5] = (mb & 32u)  ? -1e9f : s1.y * sc;
    v[6] = (mb & 64u)  ? -1e9f : s1.z * sc;
    v[7] = (mb & 128u) ? -1e9f : s1.w * sc;

    float mx = v[0];
#pragma unroll
    for (int i = 1; i < 8; i++) mx = fmaxf(mx, v[i]);
#pragma unroll
    for (int o = 16; o; o >>= 1) mx = fmaxf(mx, __shfl_xor_sync(0xffffffffu, mx, o));
    __shared__ float sm_[4], ss_[4];
    int lane = tid & 31, w = tid >> 5;
    if (lane == 0) sm_[w] = mx;
    __syncthreads();
    mx = fmaxf(fmaxf(sm_[0], sm_[1]), fmaxf(sm_[2], sm_[3]));

    float e[8];
    float sum = 0.f;
#pragma unroll
    for (int i = 0; i < 8; i++) { e[i] = __expf(v[i] - mx); sum += e[i]; }
#pragma unroll
    for (int o = 16; o; o >>= 1) sum += __shfl_xor_sync(0xffffffffu, sum, o);
    if (lane == 0) ss_[w] = sum;
    __syncthreads();
    sum = ss_[0] + ss_[1] + ss_[2] + ss_[3];
    float inv = 1.0f / sum;
    *(float4*)(row + c0) = make_float4(to_tf32(e[0] * inv), to_tf32(e[1] * inv),
                                       to_tf32(e[2] * inv), to_tf32(e[3] * inv));
    *(float4*)(row + c0 + 4) = make_float4(to_tf32(e[4] * inv), to_tf32(e[5] * inv),
                                           to_tf32(e[6] * inv), to_tf32(e[7] * inv));
}

static float* symaddr(const void* sym)
{
    void* p = nullptr;
    cudaGetSymbolAddress(&p, sym);
    return (float*)p;
}

// Dynamic smem: 3 stages * (128+BN) * 36 floats
static constexpr int smemBytes(int BN) { return 3 * (128 + BN) * 36 * 4; }

extern "C" void kernel_launch(void* const* d_in, const int* in_sizes, int n_in,
                              void* d_out, int out_size)
{
    const float* Qin  = (const float*)d_in[0];
    const float* Kin  = (const float*)d_in[1];
    const float* Vin  = (const float*)d_in[2];
    const float* Tin  = (const float*)d_in[3];
    const int*   mask = (const int*)d_in[4];
    const float* WQ = (const float*)d_in[5];
    const float* bQ = (const float*)d_in[6];
    const float* WK = (const float*)d_in[7];
    const float* bK = (const float*)d_in[8];
    const float* WV = (const float*)d_in[9];
    const float* bV = (const float*)d_in[10];
    const float* WM = (const float*)d_in[11];
    const float* bM = (const float*)d_in[12];
    const float* WT = (const float*)d_in[13];
    const float* bT = (const float*)d_in[14];
    float* out = (float*)d_out;

    float* q  = symaddr(g_q);
    float* k  = symaddr(g_k);
    float* vt = symaddr(g_vt);
    float* t  = symaddr(g_t);
    float* TT = symaddr(g_TT);
    float* S  = symaddr(g_S);
    float* x  = symaddr(g_x);
    unsigned* mp = (unsigned*)symaddr(g_mp);
    float* rQ = symaddr(g_rQ);
    float* rK = symaddr(g_rK);
    float* rV = symaddr(g_rV);
    float* rW = symaddr(g_rW);

    const int M = BB * LL;  // 8192
    dim3 gProj(DM / 128, M / 128, 1);  // (8, 64)
    const int SM128 = smemBytes(128);  // 110592
    const int SM64  = smemBytes(64);   // 82944

    static int attrDone = 0;
    if (!attrDone) {
        cudaFuncSetAttribute(wgemm<128, 32, EPI_HEADS,  true,  false, true>,
                             cudaFuncAttributeMaxDynamicSharedMemorySize, SM128);
        cudaFuncSetAttribute(wgemm<128, 32, EPI_HEADST, true,  false, true>,
                             cudaFuncAttributeMaxDynamicSharedMemorySize, SM128);
        cudaFuncSetAttribute(wgemm<128, 32, EPI_PLAIN,  false, false, false>,
                             cudaFuncAttributeMaxDynamicSharedMemorySize, SM128);
        cudaFuncSetAttribute(wgemm<128, 32, EPI_PLAIN,  false, true,  false>,
                             cudaFuncAttributeMaxDynamicSharedMemorySize, SM128);
        cudaFuncSetAttribute(wgemm<128, 32, EPI_PLAIN,  true,  false, false>,
                             cudaFuncAttributeMaxDynamicSharedMemorySize, SM128);
        cudaFuncSetAttribute(wgemm<64, 16, EPI_X, false, false, true>,
                             cudaFuncAttributeMaxDynamicSharedMemorySize, SM64);
        attrDone = 1;
    }

    // 0: tf32 pre-rounding of external GEMM operands (idempotent copies)
    const int nAct4 = BB * LL * DM / 4;   // 2,097,152 float4
    const int nW4   = DM * DM / 4;        // 262,144 float4
    round_pass<<<nAct4 / 256, 256>>>(Qin, rQ);
    round_pass<<<nAct4 / 256, 256>>>(Kin, rK);
    round_pass<<<nAct4 / 256, 256>>>(Vin, rV);
    round_pass<<<nW4 / 256, 256>>>(WQ, rW + 0L * DM * DM);
    round_pass<<<nW4 / 256, 256>>>(WK, rW + 1L * DM * DM);
    round_pass<<<nW4 / 256, 256>>>(WV, rW + 2L * DM * DM);
    round_pass<<<nW4 / 256, 256>>>(WM, rW + 3L * DM * DM);

    mask_pack<<<BB * LL * (LL / 32) / 256, 256>>>(mask, mp);

    // 1-3: Q/K/V projections (tf32). q,k head-split; v head-split + transposed.
    wgemm<128, 32, EPI_HEADS, true, false, true><<<gProj, 256, SM128>>>(
        rQ, rW + 0L * DM * DM, bQ, nullptr, q, M, DM, DM, 0, 0, 0, 0);
    wgemm<128, 32, EPI_HEADS, true, false, true><<<gProj, 256, SM128>>>(
        rK, rW + 1L * DM * DM, bK, nullptr, k, M, DM, DM, 0, 0, 0, 0);
    wgemm<128, 32, EPI_HEADST, true, false, true><<<gProj, 256, SM128>>>(
        rV, rW + 2L * DM * DM, bV, nullptr, vt, M, DM, DM, 0, 0, 0, 0);

    // 4: temporal projection t = T @ WT.T + bT (tf32-rounded output)
    tproj<<<M / 4, 256>>>(Tin, WT, bT, t);

    // 5: TT[b,q,k] = t[b,q,:].t[b,k,:]  (fp32 result, used as accumulator init)
    wgemm<128, 32, EPI_PLAIN, false, false, false><<<dim3(8, 8, BB), 256, SM128>>>(
        t, t, nullptr, nullptr, TT, LL, LL, DTT,
        (long)LL * DTT, (long)LL * DTT, (long)LL * LL, 0);

    // 6: S[bh,q,k] = q.k (64-dim) + TT[b,q,k]
    wgemm<128, 32, EPI_PLAIN, false, true, false><<<dim3(8, 8, BB * NH), 256, SM128>>>(
        q, k, nullptr, TT, S, LL, LL, DV,
        (long)LL * DV, (long)LL * DV, (long)LL * LL, (long)LL * LL);

    // 7: scale + mask + softmax, in place (P rounded to tf32)
    softmax_kernel<<<BB * NH * LL, 128>>>(S, mp);

    // 8: x[b,q,h*64+d] = P @ Vt^T  (NT, N=64); x rounded to tf32
    wgemm<64, 16, EPI_X, false, false, true><<<dim3(1, 8, BB * NH), 256, SM64>>>(
        S, vt, nullptr, nullptr, x, LL, DV, LL,
        (long)LL * LL, (long)DV * LL, 0, 0);

    // 9: out = x @ WM.T + bM
    wgemm<128, 32, EPI_PLAIN, true, false, false><<<gProj, 256, SM128>>>(
        x, rW + 3L * DM * DM, bM, nullptr, out, M, DM, DM, 0, 0, 0, 0);
}

// round 12
// speedup vs baseline: 2.7029x; 1.6914x over previous
#include <cuda_runtime.h>
#include <cuda_fp16.h>
#include <mma.h>
using namespace nvcuda;

// Problem constants
#define BB 8
#define LL 1024
#define DM 1024
#define NH 16
#define DV 64
#define DTT 64

// Scratch (device globals: allocation-free contract)
__device__ __half g_q[BB * NH * LL * DV];            // 16 MB (b,h,l,64) fp16
__device__ __half g_k[BB * NH * LL * DV];            // 16 MB
__device__ __half g_vt[BB * NH * DV * LL];           // 16 MB (b,h,d,l) V^T fp16
__device__ __half g_t[BB * LL * DTT];                // 1 MB
__device__ float  g_TT[BB * LL * LL];                // 32 MB (b,q,k) shared across heads
__device__ float  g_S[(size_t)BB * NH * LL * LL];    // 512 MB fp32 scores
__device__ __half g_Ph[(size_t)BB * NH * LL * LL];   // 256 MB fp16 probabilities
__device__ __half g_x[BB * LL * DM];                 // 16 MB
__device__ unsigned g_mp[BB * LL * (LL / 32)];       // 1 MB packed mask
__device__ __half g_rQ[BB * LL * DM];                // 16 MB fp16 input copies
__device__ __half g_rK[BB * LL * DM];
__device__ __half g_rV[BB * LL * DM];
__device__ __half g_rW[4 * DM * DM];                 // 8 MB: WQ,WK,WV,WM fp16

enum { EPI_PLAIN = 0, EPI_HEADS = 1, EPI_HEADST = 2, EPI_X = 3 };

__device__ __forceinline__ unsigned smem_u32(const void* p)
{
    return (unsigned)__cvta_generic_to_shared(p);
}
#define CP16(dst, src) \
    asm volatile("cp.async.cg.shared.global [%0], [%1], 16;" ::"r"(dst), "l"(src))
#define CP_COMMIT() asm volatile("cp.async.commit_group;")
#define CP_WAIT1() asm volatile("cp.async.wait_group 1;")
#define CP_WAIT0() asm volatile("cp.async.wait_group 0;")

// C[m,n] = sum_k A[m,k]*B[n,k] (NT) fp16 tensor cores (fp32 acc),
// 3-stage cp.async ring, one __syncthreads per K-tile.
// BM=128, BK=32, 256 threads = 8 warps as 2(m) x 4(n); warp tile 64 x WN.
template <int BN, int WN, int EPI, bool HAS_BIAS, bool ADD_INIT, bool OUT_HALF>
__global__ void __launch_bounds__(256, 2)
hgemm(const __half* __restrict__ A, const __half* __restrict__ B,
      const float* __restrict__ bias, const float* __restrict__ addend,
      void* __restrict__ Cv, int M, int N, int K,
      long aBS, long bBS, long cBS, long addBS)
{
    constexpr int BM = 128, BK = 32, LDS_ = BK + 8;  // 40 halves (mult of 8)
    constexpr int WM = 64;
    constexpr int MI = WM / 16;   // 4
    constexpr int NI = WN / 16;   // 2 (BN=128) or 1 (BN=64)
    static_assert((BM / WM) * (BN / WN) == 8, "8 warps");

    extern __shared__ char sraw[];
    __half* AS = (__half*)sraw;               // [3][BM][LDS_]
    __half* BS = AS + 3 * BM * LDS_;          // [3][BN][LDS_]

    const int z = blockIdx.z;
    A += (long)z * aBS;
    B += (long)z * bBS;
    const int m0 = blockIdx.y * BM;
    const int n0 = blockIdx.x * BN;
    const int tid = threadIdx.x;
    const int w = tid >> 5;
    const int wm = w >> 2;   // 0..1
    const int wn = w & 3;    // 0..3

    wmma::fragment<wmma::accumulator, 16, 16, 16, float> acc[MI][NI];

    if (HAS_BIAS) {
        float* fs = (float*)sraw;  // scratch before tiles are loaded
        for (int i = tid; i < 16 * BN; i += 256)
            fs[(i / BN) * (BN + 4) + (i % BN)] = bias[n0 + (i % BN)];
        __syncthreads();
#pragma unroll
        for (int i = 0; i < MI; i++)
#pragma unroll
            for (int j = 0; j < NI; j++)
                wmma::load_matrix_sync(acc[i][j], &fs[wn * WN + j * 16],
                                       BN + 4, wmma::mem_row_major);
        __syncthreads();
    } else if (ADD_INIT) {
        const float* ad = addend + (long)(z >> 4) * addBS;
#pragma unroll
        for (int i = 0; i < MI; i++) {
            int mm = m0 + wm * WM + i * 16;
#pragma unroll
            for (int j = 0; j < NI; j++) {
                int nn = n0 + wn * WN + j * 16;
                wmma::load_matrix_sync(acc[i][j], ad + (long)mm * N + nn, N,
                                       wmma::mem_row_major);
            }
        }
    } else {
#pragma unroll
        for (int i = 0; i < MI; i++)
#pragma unroll
            for (int j = 0; j < NI; j++)
                wmma::fill_fragment(acc[i][j], 0.0f);
    }

    // Tile loader: one 16B cp.async covers 8 halves; 64 rows per pass.
    const int ldrow = tid >> 2;          // 0..63
    const int ldcol = (tid & 3) << 3;    // 0,8,16,24 halves
    const __half* Ald = A + (long)(m0 + ldrow) * K + ldcol;
    const __half* Bld = B + (long)(n0 + ldrow) * K + ldcol;

    const int ntiles = K / BK;

    auto load_tile = [&](int st, int t) {
        const int kt = t * BK;
        __half* as = AS + (st * BM + ldrow) * LDS_ + ldcol;
        __half* bs = BS + (st * BN + ldrow) * LDS_ + ldcol;
#pragma unroll
        for (int r = 0; r < BM; r += 64)
            CP16(smem_u32(as + r * LDS_), Ald + (long)r * K + kt);
#pragma unroll
        for (int r = 0; r < BN; r += 64)
            CP16(smem_u32(bs + r * LDS_), Bld + (long)r * K + kt);
    };

    load_tile(0, 0);
    CP_COMMIT();
    if (ntiles > 1) {
        load_tile(1, 1);
        CP_COMMIT();
    }

    for (int t = 0; t < ntiles; ++t) {
        if (t < ntiles - 1) CP_WAIT1(); else CP_WAIT0();
        __syncthreads();   // tile t visible; all compute(t-1) finished

        if (t + 2 < ntiles) {
            load_tile((t + 2) % 3, t + 2);
            CP_COMMIT();
        }

        const int cur = t % 3;
        const __half* asBase = AS + (cur * BM + wm * WM) * LDS_;
        const __half* bsBase = BS + (cur * BN + wn * WN) * LDS_;
#pragma unroll
        for (int kk = 0; kk < BK; kk += 16) {
            wmma::fragment<wmma::matrix_a, 16, 16, 16, __half, wmma::row_major> af[MI];
            wmma::fragment<wmma::matrix_b, 16, 16, 16, __half, wmma::col_major> bf[NI];
#pragma unroll
            for (int i = 0; i < MI; i++)
                wmma::load_matrix_sync(af[i], asBase + i * 16 * LDS_ + kk, LDS_);
#pragma unroll
            for (int j = 0; j < NI; j++)
                wmma::load_matrix_sync(bf[j], bsBase + j * 16 * LDS_ + kk, LDS_);
#pragma unroll
            for (int i = 0; i < MI; i++)
#pragma unroll
                for (int j = 0; j < NI; j++)
                    wmma::mma_sync(acc[i][j], af[i], bf[j], acc[i][j]);
        }
    }

    // Epilogue
#pragma unroll
    for (int i = 0; i < MI; i++) {
        int mm = m0 + wm * WM + i * 16;
#pragma unroll
        for (int j = 0; j < NI; j++) {
            int nn = n0 + wn * WN + j * 16;
            if (OUT_HALF) {
                // fp32-acc -> fp16-acc elementwise (standard conversion pattern)
                wmma::fragment<wmma::accumulator, 16, 16, 16, __half> h;
#pragma unroll
                for (int e = 0; e < h.num_elements; e++)
                    h.x[e] = __float2half(acc[i][j].x[e]);
                __half* C = (__half*)Cv;
                if (EPI == EPI_HEADS) {
                    int b_ = mm >> 10, l_ = mm & 1023, h_ = nn >> 6, d_ = nn & 63;
                    wmma::store_matrix_sync(
                        C + (((long)(b_ * NH + h_) << 10) + l_) * 64 + d_,
                        h, 64, wmma::mem_row_major);
                } else if (EPI == EPI_HEADST) {
                    int b_ = mm >> 10, l_ = mm & 1023, h_ = nn >> 6, d_ = nn & 63;
                    wmma::store_matrix_sync(
                        C + ((long)((b_ * NH + h_) * 64 + d_) << 10) + l_,
                        h, 1024, wmma::mem_col_major);
                } else {  // EPI_X
                    int b_ = z >> 4, h_ = z & 15;
                    wmma::store_matrix_sync(
                        C + (((long)(b_ << 10) + mm) << 10) + h_ * 64 + nn,
                        h, 1024, wmma::mem_row_major);
                }
            } else {
                float* C = (float*)Cv;
                wmma::store_matrix_sync(C + (long)z * cBS + (long)mm * N + nn,
                                        acc[i][j], N, wmma::mem_row_major);
            }
        }
    }
}

// fp32 -> fp16 conversion pass: 8 elements per thread.
__global__ void __launch_bounds__(256)
f2h(const float* __restrict__ in, __half* __restrict__ out)
{
    long i = ((long)blockIdx.x * 256 + threadIdx.x) * 8;
    float4 a = *(const float4*)(in + i);
    float4 b = *(const float4*)(in + i + 4);
    struct alignas(16) H8 { __half2 v[4]; } h;
    h.v[0] = __floats2half2_rn(a.x, a.y);
    h.v[1] = __floats2half2_rn(a.z, a.w);
    h.v[2] = __floats2half2_rn(b.x, b.y);
    h.v[3] = __floats2half2_rn(b.z, b.w);
    *(H8*)(out + i) = h;
}

// t_out[b*L+l, dt] = sum_k T[b*L+l,k]*WT[dt,k] + bT[dt]  (tiny), fp16 out
__global__ void __launch_bounds__(256)
tproj(const float* __restrict__ T, const float* __restrict__ WT,
      const float* __restrict__ bT, __half* __restrict__ t_out)
{
    __shared__ float Ws[64][65];
    __shared__ float Ts[4][64];
    int tid = threadIdx.x;
    for (int i = tid; i < 64 * 64; i += 256) Ws[i >> 6][i & 63] = WT[i];
    int r0 = blockIdx.x * 4;
    Ts[tid >> 6][tid & 63] = T[r0 * 64 + tid];
    __syncthreads();
    int lr = tid >> 6, dt = tid & 63;
    float s = bT[dt];
#pragma unroll
    for (int k2 = 0; k2 < 64; k2++) s += Ts[lr][k2] * Ws[dt][k2];
    t_out[(r0 + lr) * 64 + dt] = __float2half(s);
}

// Pack mask (b,1,L,L) int32 -> 1 bit per element.
__global__ void __launch_bounds__(256)
mask_pack(const int* __restrict__ mask, unsigned* __restrict__ mp)
{
    long g = (long)blockIdx.x * 256 + threadIdx.x;
    const int4* src = (const int4*)(mask + g * 32);
    unsigned bits = 0;
#pragma unroll
    for (int i = 0; i < 8; i++) {
        int4 m = src[i];
        bits |= (unsigned)(m.x == 1) << (i * 4 + 0);
        bits |= (unsigned)(m.y == 1) << (i * 4 + 1);
        bits |= (unsigned)(m.z == 1) << (i * 4 + 2);
        bits |= (unsigned)(m.w == 1) << (i * 4 + 3);
    }
    mp[g] = bits;
}

// Row softmax with scale + packed mask: reads fp32 S, writes fp16 P.
__global__ void __launch_bounds__(128)
softmax_kernel(const float* __restrict__ S, const unsigned* __restrict__ mp,
               __half* __restrict__ P)
{
    long r = blockIdx.x;                  // r = bh*1024 + q
    int q = (int)(r & 1023);
    int b = (int)(r >> 14);               // bh >> 4
    const float* row = S + (r << 10);
    const unsigned* mrow = mp + ((((long)b) << 10) + q) * 32;
    int tid = threadIdx.x;
    int c0 = tid * 8;
    float4 s0 = *(const float4*)(row + c0);
    float4 s1 = *(const float4*)(row + c0 + 4);
    unsigned mb = (mrow[tid >> 2] >> ((tid & 3) * 8)) & 0xffu;
    const float sc = 0.08838834764831845f;  // 1/sqrt(128)
    float v[8];
    v[0] = (mb & 1u)   ? -1e9f : s0.x * sc;
    v[1] = (mb & 2u)   ? -1e9f : s0.y * sc;
    v[2] = (mb & 4u)   ? -1e9f : s0.z * sc;
    v[3] = (mb & 8u)   ? -1e9f : s0.w * sc;
    v[4] = (mb & 16u)  ? -1e9f : s1.x * sc;
    v[5] = (mb & 32u)  ? -1e9f : s1.y * sc;
    v[6] = (mb & 64u)  ? -1e9f : s1.z * sc;
    v[7] = (mb & 128u) ? -1e9f : s1.w * sc;

    float mx = v[0];
#pragma unroll
    for (int i = 1; i < 8; i++) mx = fmaxf(mx, v[i]);
#pragma unroll
    for (int o = 16; o; o >>= 1) mx = fmaxf(mx, __shfl_xor_sync(0xffffffffu, mx, o));
    __shared__ float sm_[4], ss_[4];
    int lane = tid & 31, w = tid >> 5;
    if (lane == 0) sm_[w] = mx;
    __syncthreads();
    mx = fmaxf(fmaxf(sm_[0], sm_[1]), fmaxf(sm_[2], sm_[3]));

    float e[8];
    float sum = 0.f;
#pragma unroll
    for (int i = 0; i < 8; i++) { e[i] = __expf(v[i] - mx); sum += e[i]; }
#pragma unroll
    for (int o = 16; o; o >>= 1) sum += __shfl_xor_sync(0xffffffffu, sum, o);
    if (lane == 0) ss_[w] = sum;
    __syncthreads();
    sum = ss_[0] + ss_[1] + ss_[2] + ss_[3];
    float inv = 1.0f / sum;
    struct alignas(16) H8 { __half2 v[4]; } h;
    h.v[0] = __floats2half2_rn(e[0] * inv, e[1] * inv);
    h.v[1] = __floats2half2_rn(e[2] * inv, e[3] * inv);
    h.v[2] = __floats2half2_rn(e[4] * inv, e[5] * inv);
    h.v[3] = __floats2half2_rn(e[6] * inv, e[7] * inv);
    *(H8*)(P + (r << 10) + c0) = h;
}

template <typename T>
static T* symaddr_t(const void* sym)
{
    void* p = nullptr;
    cudaGetSymbolAddress(&p, sym);
    return (T*)p;
}

// Dynamic smem: 3 stages * (128+BN) * 40 halves
static constexpr int smemBytes(int BN) { return 3 * (128 + BN) * 40 * 2; }

extern "C" void kernel_launch(void* const* d_in, const int* in_sizes, int n_in,
                              void* d_out, int out_size)
{
    const float* Qin  = (const float*)d_in[0];
    const float* Kin  = (const float*)d_in[1];
    const float* Vin  = (const float*)d_in[2];
    const float* Tin  = (const float*)d_in[3];
    const int*   mask = (const int*)d_in[4];
    const float* WQ = (const float*)d_in[5];
    const float* bQ = (const float*)d_in[6];
    const float* WK = (const float*)d_in[7];
    const float* bK = (const float*)d_in[8];
    const float* WV = (const float*)d_in[9];
    const float* bV = (const float*)d_in[10];
    const float* WM = (const float*)d_in[11];
    const float* bM = (const float*)d_in[12];
    const float* WT = (const float*)d_in[13];
    const float* bT = (const float*)d_in[14];
    float* out = (float*)d_out;

    __half* q  = symaddr_t<__half>(g_q);
    __half* k  = symaddr_t<__half>(g_k);
    __half* vt = symaddr_t<__half>(g_vt);
    __half* t  = symaddr_t<__half>(g_t);
    float*  TT = symaddr_t<float>(g_TT);
    float*  S  = symaddr_t<float>(g_S);
    __half* Ph = symaddr_t<__half>(g_Ph);
    __half* x  = symaddr_t<__half>(g_x);
    unsigned* mp = symaddr_t<unsigned>(g_mp);
    __half* rQ = symaddr_t<__half>(g_rQ);
    __half* rK = symaddr_t<__half>(g_rK);
    __half* rV = symaddr_t<__half>(g_rV);
    __half* rW = symaddr_t<__half>(g_rW);

    const int M = BB * LL;  // 8192
    dim3 gProj(DM / 128, M / 128, 1);  // (8, 64)
    const int SM128 = smemBytes(128);  // 61440
    const int SM64  = smemBytes(64);   // 46080

    static int attrDone = 0;
    if (!attrDone) {
        cudaFuncSetAttribute(hgemm<128, 32, EPI_HEADS,  true,  false, true>,
                             cudaFuncAttributeMaxDynamicSharedMemorySize, SM128);
        cudaFuncSetAttribute(hgemm<128, 32, EPI_HEADST, true,  false, true>,
                             cudaFuncAttributeMaxDynamicSharedMemorySize, SM128);
        cudaFuncSetAttribute(hgemm<128, 32, EPI_PLAIN,  false, false, false>,
                             cudaFuncAttributeMaxDynamicSharedMemorySize, SM128);
        cudaFuncSetAttribute(hgemm<128, 32, EPI_PLAIN,  false, true,  false>,
                             cudaFuncAttributeMaxDynamicSharedMemorySize, SM128);
        cudaFuncSetAttribute(hgemm<128, 32, EPI_PLAIN,  true,  false, false>,
                             cudaFuncAttributeMaxDynamicSharedMemorySize, SM128);
        cudaFuncSetAttribute(hgemm<64, 16, EPI_X, false, false, true>,
                             cudaFuncAttributeMaxDynamicSharedMemorySize, SM64);
        attrDone = 1;
    }

    // 0: fp16 conversion of external GEMM operands
    const long nAct = (long)BB * LL * DM;  // 8M
    const long nW   = (long)DM * DM;       // 1M
    f2h<<<(int)(nAct / 2048), 256>>>(Qin, rQ);
    f2h<<<(int)(nAct / 2048), 256>>>(Kin, rK);
    f2h<<<(int)(nAct / 2048), 256>>>(Vin, rV);
    f2h<<<(int)(nW / 2048), 256>>>(WQ, rW + 0L * DM * DM);
    f2h<<<(int)(nW / 2048), 256>>>(WK, rW + 1L * DM * DM);
    f2h<<<(int)(nW / 2048), 256>>>(WV, rW + 2L * DM * DM);
    f2h<<<(int)(nW / 2048), 256>>>(WM, rW + 3L * DM * DM);

    mask_pack<<<BB * LL * (LL / 32) / 256, 256>>>(mask, mp);

    // 1-3: Q/K/V projections (fp16). q,k head-split; v head-split + transposed.
    hgemm<128, 32, EPI_HEADS, true, false, true><<<gProj, 256, SM128>>>(
        rQ, rW + 0L * DM * DM, bQ, nullptr, q, M, DM, DM, 0, 0, 0, 0);
    hgemm<128, 32, EPI_HEADS, true, false, true><<<gProj, 256, SM128>>>(
        rK, rW + 1L * DM * DM, bK, nullptr, k, M, DM, DM, 0, 0, 0, 0);
    hgemm<128, 32, EPI_HEADST, true, false, true><<<gProj, 256, SM128>>>(
        rV, rW + 2L * DM * DM, bV, nullptr, vt, M, DM, DM, 0, 0, 0, 0);

    // 4: temporal projection t = T @ WT.T + bT (fp16 output)
    tproj<<<M / 4, 256>>>(Tin, WT, bT, t);

    // 5: TT[b,q,k] = t[b,q,:].t[b,k,:]  (fp32 result, accumulator init for S)
    hgemm<128, 32, EPI_PLAIN, false, false, false><<<dim3(8, 8, BB), 256, SM128>>>(
        t, t, nullptr, nullptr, TT, LL, LL, DTT,
        (long)LL * DTT, (long)LL * DTT, (long)LL * LL, 0);

    // 6: S[bh,q,k] = q.k (64-dim) + TT[b,q,k]
    hgemm<128, 32, EPI_PLAIN, false, true, false><<<dim3(8, 8, BB * NH), 256, SM128>>>(
        q, k, nullptr, TT, S, LL, LL, DV,
        (long)LL * DV, (long)LL * DV, (long)LL * LL, (long)LL * LL);

    // 7: scale + mask + softmax: fp32 S -> fp16 P
    softmax_kernel<<<BB * NH * LL, 128>>>(S, mp, Ph);

    // 8: x[b,q,h*64+d] = P @ Vt^T  (NT, N=64), fp16 out
    hgemm<64, 16, EPI_X, false, false, true><<<dim3(1, 8, BB * NH), 256, SM64>>>(
        Ph, vt, nullptr, nullptr, x, LL, DV, LL,
        (long)LL * LL, (long)DV * LL, 0, 0);

    // 9: out = x @ WM.T + bM (fp32 output)
    hgemm<128, 32, EPI_PLAIN, true, false, false><<<gProj, 256, SM128>>>(
        x, rW + 3L * DM * DM, bM, nullptr, out, M, DM, DM, 0, 0, 0, 0);
}